// round 3
// baseline (speedup 1.0000x reference)
#include <cuda_runtime.h>
#include <math.h>
#include <stddef.h>

static constexpr int CB  = 8;     // batch
static constexpr int CNQ = 1024;  // query tokens
static constexpr int CNK = 2048;  // key tokens
static constexpr int CD  = 1024;  // model dim (DQ = DK = DV)
static constexpr int CH  = 8;     // heads
static constexpr int CDH = 128;   // head dim

// ---------------- scratch (no allocations allowed -> device globals) -------
__device__ float g_q[CB * CNQ * CD];  // 32 MB
__device__ float g_k[CB * CNK * CD];  // 64 MB
__device__ float g_v[CB * CNK * CD];  // 64 MB
__device__ float g_x[CB * CNQ * CD];  // 32 MB  (attention out / LN0 out)
__device__ float g_y[CB * CNQ * CD];  // 32 MB  (pre-LN1)

// ===========================================================================
// SGEMM: C[M,1024] = A[M,1024] @ W[1024,1024] + bias            (mode 0)
//        C = R + relu(A @ W + bias)                              (mode 1)
// 128x128 tile, BK=8, 256 threads, 8x8 per-thread microtile.
// ===========================================================================
__global__ __launch_bounds__(256, 2)
void gemm_kernel(const float* __restrict__ A, const float* __restrict__ W,
                 const float* __restrict__ bias, const float* __restrict__ R,
                 float* __restrict__ C, int relu_residual)
{
    const int N = 1024, K = 1024;
    __shared__ float As[8][128];   // A tile transposed: As[k][row]
    __shared__ float Bs[8][128];   // W tile: Bs[k][col]

    const int tid = threadIdx.x;
    const int tx = tid & 15;        // 0..15  (col group)
    const int ty = tid >> 4;        // 0..15  (row group)
    const int r0 = blockIdx.y * 128;
    const int n0 = blockIdx.x * 128;

    const int arow = tid >> 1;          // 0..127
    const int aoff = (tid & 1) * 4;     // 0 or 4
    const int brow = tid >> 5;          // 0..7
    const int bcol = (tid & 31) * 4;    // 0..124

    const float* Ap = A + (size_t)(r0 + arow) * K + aoff;
    const float* Wp = W + (size_t)brow * N + n0 + bcol;

    float acc[8][8];
#pragma unroll
    for (int i = 0; i < 8; ++i)
#pragma unroll
        for (int j = 0; j < 8; ++j) acc[i][j] = 0.f;

    for (int kt = 0; kt < K / 8; ++kt) {
        float4 av = *(const float4*)(Ap + kt * 8);
        float4 bv = *(const float4*)(Wp + (size_t)kt * 8 * N);
        __syncthreads();                 // previous iter's compute done
        As[aoff + 0][arow] = av.x;
        As[aoff + 1][arow] = av.y;
        As[aoff + 2][arow] = av.z;
        As[aoff + 3][arow] = av.w;
        *(float4*)&Bs[brow][bcol] = bv;
        __syncthreads();                 // tiles visible
#pragma unroll
        for (int kk = 0; kk < 8; ++kk) {
            float4 a0 = *(const float4*)&As[kk][ty * 4];
            float4 a1 = *(const float4*)&As[kk][64 + ty * 4];
            float4 b0 = *(const float4*)&Bs[kk][tx * 4];
            float4 b1 = *(const float4*)&Bs[kk][64 + tx * 4];
            float ar[8] = {a0.x, a0.y, a0.z, a0.w, a1.x, a1.y, a1.z, a1.w};
            float br[8] = {b0.x, b0.y, b0.z, b0.w, b1.x, b1.y, b1.z, b1.w};
#pragma unroll
            for (int i = 0; i < 8; ++i)
#pragma unroll
                for (int j = 0; j < 8; ++j)
                    acc[i][j] = fmaf(ar[i], br[j], acc[i][j]);
        }
    }

#pragma unroll
    for (int hi = 0; hi < 2; ++hi)
#pragma unroll
    for (int ii = 0; ii < 4; ++ii) {
        const int r  = r0 + hi * 64 + ty * 4 + ii;
        const int ci = hi * 4 + ii;
#pragma unroll
        for (int hj = 0; hj < 2; ++hj) {
            const int cc = n0 + hj * 64 + tx * 4;
            float4 bb = *(const float4*)(bias + cc);
            float4 val;
            val.x = acc[ci][hj * 4 + 0] + bb.x;
            val.y = acc[ci][hj * 4 + 1] + bb.y;
            val.z = acc[ci][hj * 4 + 2] + bb.z;
            val.w = acc[ci][hj * 4 + 3] + bb.w;
            if (relu_residual) {
                float4 rr = *(const float4*)(R + (size_t)r * N + cc);
                val.x = rr.x + fmaxf(val.x, 0.f);
                val.y = rr.y + fmaxf(val.y, 0.f);
                val.z = rr.z + fmaxf(val.z, 0.f);
                val.w = rr.w + fmaxf(val.w, 0.f);
            }
            *(float4*)(C + (size_t)r * N + cc) = val;
        }
    }
}

// ===========================================================================
// Flash-style attention per (b, h, 64-q-row block).
// x[b, q, h*128 + d] = qh + softmax(qh kh^T / 32) vh
// Smem: Qt[128][64] (transposed), KV (Kt[128][64] then Vs[64][128]), Pt[64][65]
// ===========================================================================
static constexpr int ATT_SMEM_FLOATS = 128 * 64 + 128 * 64 + 64 * 65;
static constexpr int ATT_SMEM_BYTES  = ATT_SMEM_FLOATS * 4;   // 82176 B

__global__ __launch_bounds__(256, 2)
void attn_kernel(const float* __restrict__ q, const float* __restrict__ k,
                 const float* __restrict__ v, float* __restrict__ x)
{
    extern __shared__ float sm[];
    float* Qt = sm;               // [128][64]  Qt[d*64 + i]
    float* KV = sm + 8192;        // Kt[d*64+j] or Vs[j*128+d]
    float* Pt = sm + 16384;       // [64][65]   Pt[j*65 + i]

    const int b  = blockIdx.z;
    const int h  = blockIdx.y;
    const int q0 = blockIdx.x * 64;

    const float* qb = q + ((size_t)(b * CNQ + q0)) * CD + h * CDH;
    const float* kb = k + (size_t)b * CNK * CD + h * CDH;
    const float* vb = v + (size_t)b * CNK * CD + h * CDH;
    float*       xb = x + ((size_t)(b * CNQ + q0)) * CD + h * CDH;

    const int tid = threadIdx.x;
    const int tx = tid & 15;   // 0..15
    const int ty = tid >> 4;   // 0..15

    // ---- load Q block transposed ----
    {
        const int i = tid & 63, chunk = tid >> 6;   // chunk 0..3
#pragma unroll
        for (int rep = 0; rep < 8; ++rep) {
            const int d = rep * 16 + chunk * 4;
            float4 vq = *(const float4*)(qb + (size_t)i * CD + d);
            Qt[(d + 0) * 64 + i] = vq.x;
            Qt[(d + 1) * 64 + i] = vq.y;
            Qt[(d + 2) * 64 + i] = vq.z;
            Qt[(d + 3) * 64 + i] = vq.w;
        }
    }

    float m[4], l[4], o[4][8];
#pragma unroll
    for (int ii = 0; ii < 4; ++ii) {
        m[ii] = -1e30f;
        l[ii] = 0.f;
#pragma unroll
        for (int c = 0; c < 8; ++c) o[ii][c] = 0.f;
    }
    const float scale = 0.03125f;   // 1/sqrt(1024)

    for (int kt = 0; kt < CNK / 64; ++kt) {
        const int j0 = kt * 64;

        __syncthreads();  // prev O-GEMM done (and Qt load done on iter 0)

        // ---- load K tile transposed into KV ----
        {
            const int j = tid & 63, chunk = tid >> 6;
#pragma unroll
            for (int rep = 0; rep < 8; ++rep) {
                const int d = rep * 16 + chunk * 4;
                float4 kv4 = *(const float4*)(kb + (size_t)(j0 + j) * CD + d);
                KV[(d + 0) * 64 + j] = kv4.x;
                KV[(d + 1) * 64 + j] = kv4.y;
                KV[(d + 2) * 64 + j] = kv4.z;
                KV[(d + 3) * 64 + j] = kv4.w;
            }
        }
        __syncthreads();

        // ---- S = Qt^T @ Kt tile: thread holds 4 rows x 4 cols ----
        float s[4][4];
#pragma unroll
        for (int ii = 0; ii < 4; ++ii)
#pragma unroll
            for (int jj = 0; jj < 4; ++jj) s[ii][jj] = 0.f;

        for (int d = 0; d < 128; ++d) {
            float4 qv = *(const float4*)&Qt[d * 64 + ty * 4];
            float4 kv4 = *(const float4*)&KV[d * 64 + tx * 4];
            float qr[4] = {qv.x, qv.y, qv.z, qv.w};
            float kr[4] = {kv4.x, kv4.y, kv4.z, kv4.w};
#pragma unroll
            for (int ii = 0; ii < 4; ++ii)
#pragma unroll
                for (int jj = 0; jj < 4; ++jj)
                    s[ii][jj] = fmaf(qr[ii], kr[jj], s[ii][jj]);
        }

        // ---- online softmax update ----
        float p[4][4];
#pragma unroll
        for (int ii = 0; ii < 4; ++ii) {
            float mt = s[ii][0] * scale;
#pragma unroll
            for (int jj = 1; jj < 4; ++jj) mt = fmaxf(mt, s[ii][jj] * scale);
            // reduce max across the 16 lanes owning this row
#pragma unroll
            for (int off = 8; off >= 1; off >>= 1)
                mt = fmaxf(mt, __shfl_xor_sync(0xffffffffu, mt, off));
            const float mnew = fmaxf(m[ii], mt);
            const float alpha = __expf(m[ii] - mnew);
            float rs = 0.f;
#pragma unroll
            for (int jj = 0; jj < 4; ++jj) {
                p[ii][jj] = __expf(fmaf(s[ii][jj], scale, -mnew));
                rs += p[ii][jj];
            }
#pragma unroll
            for (int off = 8; off >= 1; off >>= 1)
                rs += __shfl_xor_sync(0xffffffffu, rs, off);
            l[ii] = l[ii] * alpha + rs;
            m[ii] = mnew;
#pragma unroll
            for (int c = 0; c < 8; ++c) o[ii][c] *= alpha;
        }

        // ---- stash P (transposed) ----
#pragma unroll
        for (int jj = 0; jj < 4; ++jj)
#pragma unroll
            for (int ii = 0; ii < 4; ++ii)
                Pt[(tx * 4 + jj) * 65 + ty * 4 + ii] = p[ii][jj];

        __syncthreads();  // Kt reads done, Pt written -> reuse KV for V

        // ---- load V tile row-major into KV ----
        {
            const int j = tid >> 2, chunk = tid & 3;
#pragma unroll
            for (int rep = 0; rep < 8; ++rep) {
                const int d = chunk * 4 + rep * 16;
                *(float4*)&KV[j * 128 + d] =
                    *(const float4*)(vb + (size_t)(j0 + j) * CD + d);
            }
        }
        __syncthreads();

        // ---- O += P @ V: thread holds 4 rows x 8 dv cols ----
        for (int j = 0; j < 64; ++j) {
            float pr[4];
#pragma unroll
            for (int ii = 0; ii < 4; ++ii) pr[ii] = Pt[j * 65 + ty * 4 + ii];
            float4 v0 = *(const float4*)&KV[j * 128 + tx * 8];
            float4 v1 = *(const float4*)&KV[j * 128 + tx * 8 + 4];
            float vr[8] = {v0.x, v0.y, v0.z, v0.w, v1.x, v1.y, v1.z, v1.w};
#pragma unroll
            for (int ii = 0; ii < 4; ++ii)
#pragma unroll
                for (int c = 0; c < 8; ++c)
                    o[ii][c] = fmaf(pr[ii], vr[c], o[ii][c]);
        }
    }

    // ---- epilogue: x = qh + O / l ----
#pragma unroll
    for (int ii = 0; ii < 4; ++ii) {
        const int i = ty * 4 + ii;
        const float inv = 1.f / l[ii];
        float4 o0, o1;
        o0.x = fmaf(o[ii][0], inv, Qt[(tx * 8 + 0) * 64 + i]);
        o0.y = fmaf(o[ii][1], inv, Qt[(tx * 8 + 1) * 64 + i]);
        o0.z = fmaf(o[ii][2], inv, Qt[(tx * 8 + 2) * 64 + i]);
        o0.w = fmaf(o[ii][3], inv, Qt[(tx * 8 + 3) * 64 + i]);
        o1.x = fmaf(o[ii][4], inv, Qt[(tx * 8 + 4) * 64 + i]);
        o1.y = fmaf(o[ii][5], inv, Qt[(tx * 8 + 5) * 64 + i]);
        o1.z = fmaf(o[ii][6], inv, Qt[(tx * 8 + 6) * 64 + i]);
        o1.w = fmaf(o[ii][7], inv, Qt[(tx * 8 + 7) * 64 + i]);
        *(float4*)(xb + (size_t)i * CD + tx * 8)     = o0;
        *(float4*)(xb + (size_t)i * CD + tx * 8 + 4) = o1;
    }
}

// ===========================================================================
// Row LayerNorm over 1024 columns. out = (x - mu) * rsqrt(var + 1e-5) * g + b
// ===========================================================================
__global__ __launch_bounds__(256)
void ln_kernel(const float* __restrict__ in, float* __restrict__ out,
               const float* __restrict__ g, const float* __restrict__ bta)
{
    __shared__ float red_s[8], red_s2[8];
    __shared__ float mu_s, rs_s;
    const int row = blockIdx.x;
    const int tid = threadIdx.x;
    const float* rp = in + (size_t)row * 1024;

    float4 xv = *(const float4*)(rp + tid * 4);
    float s  = xv.x + xv.y + xv.z + xv.w;
    float s2 = xv.x * xv.x + xv.y * xv.y + xv.z * xv.z + xv.w * xv.w;
#pragma unroll
    for (int off = 16; off >= 1; off >>= 1) {
        s  += __shfl_xor_sync(0xffffffffu, s,  off);
        s2 += __shfl_xor_sync(0xffffffffu, s2, off);
    }
    if ((tid & 31) == 0) { red_s[tid >> 5] = s; red_s2[tid >> 5] = s2; }
    __syncthreads();
    if (tid == 0) {
        float a = 0.f, a2 = 0.f;
#pragma unroll
        for (int w = 0; w < 8; ++w) { a += red_s[w]; a2 += red_s2[w]; }
        const float mu  = a * (1.f / 1024.f);
        const float var = a2 * (1.f / 1024.f) - mu * mu;
        mu_s = mu;
        rs_s = rsqrtf(var + 1e-5f);
    }
    __syncthreads();
    const float mu = mu_s, rs = rs_s;
    float4 gv = *(const float4*)(g + tid * 4);
    float4 bv = *(const float4*)(bta + tid * 4);
    float4 ov;
    ov.x = (xv.x - mu) * rs * gv.x + bv.x;
    ov.y = (xv.y - mu) * rs * gv.y + bv.y;
    ov.z = (xv.z - mu) * rs * gv.z + bv.z;
    ov.w = (xv.w - mu) * rs * gv.w + bv.w;
    *(float4*)(out + (size_t)row * 1024 + tid * 4) = ov;
}

// ===========================================================================
extern "C" void kernel_launch(void* const* d_in, const int* in_sizes, int n_in,
                              void* d_out, int out_size)
{
    const float* Q  = (const float*)d_in[0];
    const float* K  = (const float*)d_in[1];
    const float* Wq = (const float*)d_in[2];
    const float* bq = (const float*)d_in[3];
    const float* Wk = (const float*)d_in[4];
    const float* bk = (const float*)d_in[5];
    const float* Wv = (const float*)d_in[6];
    const float* bv = (const float*)d_in[7];
    const float* Wo = (const float*)d_in[8];
    const float* bo = (const float*)d_in[9];
    const float* g0 = (const float*)d_in[10];
    const float* b0 = (const float*)d_in[11];
    const float* g1 = (const float*)d_in[12];
    const float* b1 = (const float*)d_in[13];
    float* out = (float*)d_out;

    float *qp, *kp, *vp, *xp, *yp;
    cudaGetSymbolAddress((void**)&qp, g_q);
    cudaGetSymbolAddress((void**)&kp, g_k);
    cudaGetSymbolAddress((void**)&vp, g_v);
    cudaGetSymbolAddress((void**)&xp, g_x);
    cudaGetSymbolAddress((void**)&yp, g_y);

    cudaFuncSetAttribute(attn_kernel,
                         cudaFuncAttributeMaxDynamicSharedMemorySize,
                         ATT_SMEM_BYTES);

    // projections
    gemm_kernel<<<dim3(8,  64), 256>>>(Q, Wq, bq, nullptr, qp, 0);
    gemm_kernel<<<dim3(8, 128), 256>>>(K, Wk, bk, nullptr, kp, 0);
    gemm_kernel<<<dim3(8, 128), 256>>>(K, Wv, bv, nullptr, vp, 0);
    // attention + residual
    attn_kernel<<<dim3(CNQ / 64, CH, CB), 256, ATT_SMEM_BYTES>>>(qp, kp, vp, xp);
    // LN0 (in place)
    ln_kernel<<<CB * CNQ, 256>>>(xp, xp, g0, b0);
    // y = x + relu(x @ Wo + bo)
    gemm_kernel<<<dim3(8, 64), 256>>>(xp, Wo, bo, xp, yp, 1);
    // LN1 -> out
    ln_kernel<<<CB * CNQ, 256>>>(yp, out, g1, b1);
}

// round 4
// speedup vs baseline: 1.3002x; 1.3002x over previous
#include <cuda_runtime.h>
#include <mma.h>
#include <math.h>
#include <stddef.h>

using namespace nvcuda;

static constexpr int CB  = 8;     // batch
static constexpr int CNQ = 1024;  // query tokens
static constexpr int CNK = 2048;  // key tokens
static constexpr int CD  = 1024;  // model dim
static constexpr int CH  = 8;     // heads
static constexpr int CDH = 128;   // head dim

// ---------------- scratch (no allocations allowed -> device globals) -------
__device__ float g_q[CB * CNQ * CD];  // 32 MB
__device__ float g_k[CB * CNK * CD];  // 64 MB
__device__ float g_v[CB * CNK * CD];  // 64 MB
__device__ float g_x[CB * CNQ * CD];  // 32 MB
__device__ float g_y[CB * CNQ * CD];  // 32 MB

__device__ __forceinline__ float to_tf32(float x) {
    float r;
    asm("cvt.rna.tf32.f32 %0, %1;" : "=f"(r) : "f"(x));
    return r;
}

typedef wmma::fragment<wmma::matrix_a, 16, 16, 8, wmma::precision::tf32, wmma::row_major> AFrag;
typedef wmma::fragment<wmma::matrix_b, 16, 16, 8, wmma::precision::tf32, wmma::row_major> BFragRow;
typedef wmma::fragment<wmma::matrix_b, 16, 16, 8, wmma::precision::tf32, wmma::col_major> BFragCol;
typedef wmma::fragment<wmma::accumulator, 16, 16, 8, float> CFrag;

// ===========================================================================
// tf32 tensor-core GEMM: C[M,1024] = A[M,1024] @ W[1024,1024] + bias (mode 0)
//                        C = R + relu(A @ W + bias)               (mode 1)
// 128x128 tile, BK=16, 256 threads / 8 warps, warp tile 32x64.
// ===========================================================================
static constexpr int GEMM_AS_LD = 20;    // pad (mult of 4)
static constexpr int GEMM_BS_LD = 132;
static constexpr int GEMM_CS_LD = 132;
static constexpr int GEMM_SMEM_BYTES = 128 * GEMM_CS_LD * 4;  // 67584 (>= loop usage)

__global__ __launch_bounds__(256)
void gemm_tc_kernel(const float* __restrict__ A, const float* __restrict__ W,
                    const float* __restrict__ bias, const float* __restrict__ R,
                    float* __restrict__ C, int relu_residual)
{
    const int N = 1024, K = 1024;
    extern __shared__ float sm[];
    float* As = sm;                       // [128][20]
    float* Bs = sm + 128 * GEMM_AS_LD;    // [16][132]
    float* Cs = sm;                       // epilogue alias [128][132]

    const int tid = threadIdx.x;
    const int w   = tid >> 5;
    const int wm  = w & 3;       // 0..3  -> 32-row group
    const int wn  = w >> 2;      // 0..1  -> 64-col group
    const int r0  = blockIdx.y * 128;
    const int n0  = blockIdx.x * 128;

    CFrag acc[2][4];
#pragma unroll
    for (int i = 0; i < 2; ++i)
#pragma unroll
        for (int j = 0; j < 4; ++j) wmma::fill_fragment(acc[i][j], 0.f);

    const int a_row = tid >> 1;
    const int a_c0  = (tid & 1) * 8;
    const int b_row = tid >> 4;
    const int b_c0  = (tid & 15) * 8;
    const float* Ap = A + (size_t)(r0 + a_row) * K + a_c0;
    const float* Wp = W + (size_t)b_row * N + n0 + b_c0;

    for (int kt = 0; kt < K / 16; ++kt) {
        const int k0 = kt * 16;
        float4 av0 = *(const float4*)(Ap + k0);
        float4 av1 = *(const float4*)(Ap + k0 + 4);
        float4 bv0 = *(const float4*)(Wp + (size_t)k0 * N);
        float4 bv1 = *(const float4*)(Wp + (size_t)k0 * N + 4);
        __syncthreads();
        float* ap = &As[a_row * GEMM_AS_LD + a_c0];
        ap[0] = to_tf32(av0.x); ap[1] = to_tf32(av0.y);
        ap[2] = to_tf32(av0.z); ap[3] = to_tf32(av0.w);
        ap[4] = to_tf32(av1.x); ap[5] = to_tf32(av1.y);
        ap[6] = to_tf32(av1.z); ap[7] = to_tf32(av1.w);
        float* bp = &Bs[b_row * GEMM_BS_LD + b_c0];
        bp[0] = to_tf32(bv0.x); bp[1] = to_tf32(bv0.y);
        bp[2] = to_tf32(bv0.z); bp[3] = to_tf32(bv0.w);
        bp[4] = to_tf32(bv1.x); bp[5] = to_tf32(bv1.y);
        bp[6] = to_tf32(bv1.z); bp[7] = to_tf32(bv1.w);
        __syncthreads();
#pragma unroll
        for (int ks = 0; ks < 16; ks += 8) {
            AFrag af[2];
#pragma unroll
            for (int i = 0; i < 2; ++i)
                wmma::load_matrix_sync(af[i], &As[(wm * 32 + i * 16) * GEMM_AS_LD + ks], GEMM_AS_LD);
            BFragRow bf[4];
#pragma unroll
            for (int j = 0; j < 4; ++j)
                wmma::load_matrix_sync(bf[j], &Bs[ks * GEMM_BS_LD + wn * 64 + j * 16], GEMM_BS_LD);
#pragma unroll
            for (int i = 0; i < 2; ++i)
#pragma unroll
                for (int j = 0; j < 4; ++j)
                    wmma::mma_sync(acc[i][j], af[i], bf[j], acc[i][j]);
        }
    }

    __syncthreads();
#pragma unroll
    for (int i = 0; i < 2; ++i)
#pragma unroll
        for (int j = 0; j < 4; ++j)
            wmma::store_matrix_sync(&Cs[(wm * 32 + i * 16) * GEMM_CS_LD + wn * 64 + j * 16],
                                    acc[i][j], GEMM_CS_LD, wmma::mem_row_major);
    __syncthreads();

    const int er  = tid >> 1;
    const int ec0 = (tid & 1) * 64;
#pragma unroll
    for (int q = 0; q < 16; ++q) {
        const int c = ec0 + q * 4;
        float4 bb = *(const float4*)(bias + n0 + c);
        const float* cp = &Cs[er * GEMM_CS_LD + c];
        float4 val;
        val.x = cp[0] + bb.x; val.y = cp[1] + bb.y;
        val.z = cp[2] + bb.z; val.w = cp[3] + bb.w;
        if (relu_residual) {
            float4 rr = *(const float4*)(R + (size_t)(r0 + er) * N + n0 + c);
            val.x = rr.x + fmaxf(val.x, 0.f);
            val.y = rr.y + fmaxf(val.y, 0.f);
            val.z = rr.z + fmaxf(val.z, 0.f);
            val.w = rr.w + fmaxf(val.w, 0.f);
        }
        *(float4*)(C + (size_t)(r0 + er) * N + n0 + c) = val;
    }
}

// ===========================================================================
// Attention per (b, h, 64-q-row block), tf32 tensor cores, no-max softmax.
// x[b,q,h*128+d] = qh + (sum_j exp(s_j) v_j) / (sum_j exp(s_j))
// ===========================================================================
static constexpr int ATT_T_LD = 132;  // Qs / KV pad
static constexpr int ATT_P_LD = 68;   // Ps pad
static constexpr int ATT_QS_OFF = 0;                       // [64][132]
static constexpr int ATT_KV_OFF = 64 * ATT_T_LD;           // [64][132]
static constexpr int ATT_PS_OFF = 2 * 64 * ATT_T_LD;       // [64][68]
static constexpr int ATT_L_OFF  = ATT_PS_OFF + 64 * ATT_P_LD;  // [64]
static constexpr int ATT_SMEM_BYTES = (ATT_L_OFF + 64) * 4;    // 85504 B

__global__ __launch_bounds__(256, 2)
void attn_tc_kernel(const float* __restrict__ q, const float* __restrict__ k,
                    const float* __restrict__ v, float* __restrict__ x)
{
    extern __shared__ float sm[];
    float* Qs = sm + ATT_QS_OFF;
    float* KV = sm + ATT_KV_OFF;
    float* Ps = sm + ATT_PS_OFF;
    float* lrow = sm + ATT_L_OFF;

    const int b  = blockIdx.z;
    const int h  = blockIdx.y;
    const int q0 = blockIdx.x * 64;

    const float* qb = q + ((size_t)(b * CNQ + q0)) * CD + h * CDH;
    const float* kb = k + (size_t)b * CNK * CD + h * CDH;
    const float* vb = v + (size_t)b * CNK * CD + h * CDH;
    float*       xb = x + ((size_t)(b * CNQ + q0)) * CD + h * CDH;

    const int tid = threadIdx.x;
    const int w   = tid >> 5;
    const int wmS = w & 3;    // S: 16-row group
    const int wnS = w >> 2;   // S: 32-col group (2 frags)
    const int wmO = w & 3;    // PV: 16-row group
    const int wnO = w >> 2;   // PV: 64-col group (4 frags)

    // load Q tile (tf32) + init l
    {
        const int r  = tid >> 2;
        const int c0 = (tid & 3) * 32;
#pragma unroll
        for (int u = 0; u < 8; ++u) {
            float4 vq = *(const float4*)(qb + (size_t)r * CD + c0 + u * 4);
            float* p = &Qs[r * ATT_T_LD + c0 + u * 4];
            p[0] = to_tf32(vq.x); p[1] = to_tf32(vq.y);
            p[2] = to_tf32(vq.z); p[3] = to_tf32(vq.w);
        }
        if (tid < 64) lrow[tid] = 0.f;
    }

    CFrag oacc[4];
#pragma unroll
    for (int j = 0; j < 4; ++j) wmma::fill_fragment(oacc[j], 0.f);

    const float scale = 0.03125f;  // 1/sqrt(1024)

    for (int kt = 0; kt < CNK / 64; ++kt) {
        const int j0 = kt * 64;

        __syncthreads();  // prev PV done with KV (iter0: Qs/l visible)

        // ---- K tile -> KV (tf32) ----
        {
            const int r  = tid >> 2;
            const int c0 = (tid & 3) * 32;
#pragma unroll
            for (int u = 0; u < 8; ++u) {
                float4 kv4 = *(const float4*)(kb + (size_t)(j0 + r) * CD + c0 + u * 4);
                float* p = &KV[r * ATT_T_LD + c0 + u * 4];
                p[0] = to_tf32(kv4.x); p[1] = to_tf32(kv4.y);
                p[2] = to_tf32(kv4.z); p[3] = to_tf32(kv4.w);
            }
        }
        __syncthreads();

        // ---- S = Q @ K^T  (64x64) ----
        {
            CFrag sacc[2];
            wmma::fill_fragment(sacc[0], 0.f);
            wmma::fill_fragment(sacc[1], 0.f);
#pragma unroll
            for (int kk = 0; kk < 128; kk += 8) {
                AFrag af;
                wmma::load_matrix_sync(af, &Qs[(wmS * 16) * ATT_T_LD + kk], ATT_T_LD);
                BFragCol bf[2];
#pragma unroll
                for (int j = 0; j < 2; ++j)
                    wmma::load_matrix_sync(bf[j], &KV[(wnS * 32 + j * 16) * ATT_T_LD + kk], ATT_T_LD);
#pragma unroll
                for (int j = 0; j < 2; ++j)
                    wmma::mma_sync(sacc[j], af, bf[j], sacc[j]);
            }
#pragma unroll
            for (int j = 0; j < 2; ++j)
                wmma::store_matrix_sync(&Ps[(wmS * 16) * ATT_P_LD + wnS * 32 + j * 16],
                                        sacc[j], ATT_P_LD, wmma::mem_row_major);
        }
        __syncthreads();

        // ---- V tile -> KV; softmax (exp, row-sum) on Ps ----
        {
            const int r  = tid >> 2;
            const int c0 = (tid & 3) * 32;
#pragma unroll
            for (int u = 0; u < 8; ++u) {
                float4 vv = *(const float4*)(vb + (size_t)(j0 + r) * CD + c0 + u * 4);
                float* p = &KV[r * ATT_T_LD + c0 + u * 4];
                p[0] = to_tf32(vv.x); p[1] = to_tf32(vv.y);
                p[2] = to_tf32(vv.z); p[3] = to_tf32(vv.w);
            }
            const int pc0 = (tid & 3) * 16;
            float* pr = &Ps[r * ATT_P_LD + pc0];
            float sum = 0.f;
#pragma unroll
            for (int u = 0; u < 16; ++u) {
                float e = __expf(pr[u] * scale);
                sum += e;
                pr[u] = to_tf32(e);
            }
            sum += __shfl_xor_sync(0xffffffffu, sum, 1);
            sum += __shfl_xor_sync(0xffffffffu, sum, 2);
            if ((tid & 3) == 0) lrow[r] += sum;
        }
        __syncthreads();

        // ---- O += P @ V  (64x128) ----
#pragma unroll
        for (int jj = 0; jj < 64; jj += 8) {
            AFrag af;
            wmma::load_matrix_sync(af, &Ps[(wmO * 16) * ATT_P_LD + jj], ATT_P_LD);
            BFragRow bf[4];
#pragma unroll
            for (int j = 0; j < 4; ++j)
                wmma::load_matrix_sync(bf[j], &KV[jj * ATT_T_LD + wnO * 64 + j * 16], ATT_T_LD);
#pragma unroll
            for (int j = 0; j < 4; ++j)
                wmma::mma_sync(oacc[j], af, bf[j], oacc[j]);
        }
    }

    // ---- epilogue: x = q(fp32, gmem) + O / l ----
    __syncthreads();
#pragma unroll
    for (int j = 0; j < 4; ++j)
        wmma::store_matrix_sync(&KV[(wmO * 16) * ATT_T_LD + wnO * 64 + j * 16],
                                oacc[j], ATT_T_LD, wmma::mem_row_major);
    __syncthreads();
    {
        const int r  = tid >> 2;
        const int c0 = (tid & 3) * 32;
        const float inv = 1.f / lrow[r];
#pragma unroll
        for (int u = 0; u < 8; ++u) {
            const int c = c0 + u * 4;
            float4 qres = *(const float4*)(qb + (size_t)r * CD + c);
            const float* op = &KV[r * ATT_T_LD + c];
            float4 ov;
            ov.x = fmaf(op[0], inv, qres.x);
            ov.y = fmaf(op[1], inv, qres.y);
            ov.z = fmaf(op[2], inv, qres.z);
            ov.w = fmaf(op[3], inv, qres.w);
            *(float4*)(xb + (size_t)r * CD + c) = ov;
        }
    }
}

// ===========================================================================
// Row LayerNorm over 1024 columns.
// ===========================================================================
__global__ __launch_bounds__(256)
void ln_kernel(const float* __restrict__ in, float* __restrict__ out,
               const float* __restrict__ g, const float* __restrict__ bta)
{
    __shared__ float red_s[8], red_s2[8];
    __shared__ float mu_s, rs_s;
    const int row = blockIdx.x;
    const int tid = threadIdx.x;
    const float* rp = in + (size_t)row * 1024;

    float4 xv = *(const float4*)(rp + tid * 4);
    float s  = xv.x + xv.y + xv.z + xv.w;
    float s2 = xv.x * xv.x + xv.y * xv.y + xv.z * xv.z + xv.w * xv.w;
#pragma unroll
    for (int off = 16; off >= 1; off >>= 1) {
        s  += __shfl_xor_sync(0xffffffffu, s,  off);
        s2 += __shfl_xor_sync(0xffffffffu, s2, off);
    }
    if ((tid & 31) == 0) { red_s[tid >> 5] = s; red_s2[tid >> 5] = s2; }
    __syncthreads();
    if (tid == 0) {
        float a = 0.f, a2 = 0.f;
#pragma unroll
        for (int wq = 0; wq < 8; ++wq) { a += red_s[wq]; a2 += red_s2[wq]; }
        const float mu  = a * (1.f / 1024.f);
        const float var = a2 * (1.f / 1024.f) - mu * mu;
        mu_s = mu;
        rs_s = rsqrtf(var + 1e-5f);
    }
    __syncthreads();
    const float mu = mu_s, rs = rs_s;
    float4 gv = *(const float4*)(g + tid * 4);
    float4 bv = *(const float4*)(bta + tid * 4);
    float4 ov;
    ov.x = (xv.x - mu) * rs * gv.x + bv.x;
    ov.y = (xv.y - mu) * rs * gv.y + bv.y;
    ov.z = (xv.z - mu) * rs * gv.z + bv.z;
    ov.w = (xv.w - mu) * rs * gv.w + bv.w;
    *(float4*)(out + (size_t)row * 1024 + tid * 4) = ov;
}

// ===========================================================================
extern "C" void kernel_launch(void* const* d_in, const int* in_sizes, int n_in,
                              void* d_out, int out_size)
{
    const float* Q  = (const float*)d_in[0];
    const float* K  = (const float*)d_in[1];
    const float* Wq = (const float*)d_in[2];
    const float* bq = (const float*)d_in[3];
    const float* Wk = (const float*)d_in[4];
    const float* bk = (const float*)d_in[5];
    const float* Wv = (const float*)d_in[6];
    const float* bv = (const float*)d_in[7];
    const float* Wo = (const float*)d_in[8];
    const float* bo = (const float*)d_in[9];
    const float* g0 = (const float*)d_in[10];
    const float* b0 = (const float*)d_in[11];
    const float* g1 = (const float*)d_in[12];
    const float* b1 = (const float*)d_in[13];
    float* out = (float*)d_out;

    float *qp, *kp, *vp, *xp, *yp;
    cudaGetSymbolAddress((void**)&qp, g_q);
    cudaGetSymbolAddress((void**)&kp, g_k);
    cudaGetSymbolAddress((void**)&vp, g_v);
    cudaGetSymbolAddress((void**)&xp, g_x);
    cudaGetSymbolAddress((void**)&yp, g_y);

    cudaFuncSetAttribute(gemm_tc_kernel,
                         cudaFuncAttributeMaxDynamicSharedMemorySize,
                         GEMM_SMEM_BYTES);
    cudaFuncSetAttribute(attn_tc_kernel,
                         cudaFuncAttributeMaxDynamicSharedMemorySize,
                         ATT_SMEM_BYTES);

    // projections (tf32 tensor cores)
    gemm_tc_kernel<<<dim3(8,  64), 256, GEMM_SMEM_BYTES>>>(Q, Wq, bq, nullptr, qp, 0);
    gemm_tc_kernel<<<dim3(8, 128), 256, GEMM_SMEM_BYTES>>>(K, Wk, bk, nullptr, kp, 0);
    gemm_tc_kernel<<<dim3(8, 128), 256, GEMM_SMEM_BYTES>>>(K, Wv, bv, nullptr, vp, 0);
    // attention + residual
    attn_tc_kernel<<<dim3(CNQ / 64, CH, CB), 256, ATT_SMEM_BYTES>>>(qp, kp, vp, xp);
    // LN0 (in place)
    ln_kernel<<<CB * CNQ, 256>>>(xp, xp, g0, b0);
    // y = x + relu(x @ Wo + bo)
    gemm_tc_kernel<<<dim3(8, 64), 256, GEMM_SMEM_BYTES>>>(xp, Wo, bo, xp, yp, 1);
    // LN1 -> out
    ln_kernel<<<CB * CNQ, 256>>>(yp, out, g1, b1);
}

// round 7
// speedup vs baseline: 1.3650x; 1.0499x over previous
#include <cuda_runtime.h>
#include <mma.h>
#include <math.h>
#include <stddef.h>
#include <stdint.h>

using namespace nvcuda;

static constexpr int CB  = 8;     // batch
static constexpr int CNQ = 1024;  // query tokens
static constexpr int CNK = 2048;  // key tokens
static constexpr int CD  = 1024;  // model dim
static constexpr int CH  = 8;     // heads
static constexpr int CDH = 128;   // head dim

// ---------------- scratch (no allocations allowed -> device globals) -------
__device__ float g_q[CB * CNQ * CD];   // 32 MB  q projection
__device__ float g_k[CB * CNK * CD];   // 64 MB  k projection
__device__ float g_v[CB * CNK * CD];   // 64 MB  v projection
__device__ float g_x[CB * CNQ * CD];   // 32 MB  attn out / LN0 out
__device__ float g_y[CB * CNQ * CD];   // 32 MB  pre-LN1
__device__ float g_wr[4][CD * CD];     // 16 MB  tf32-rounded weights (row-major)
__device__ float g_qr[CB * CNQ * CD];  // 32 MB  tf32-rounded Q
__device__ float g_kr[CB * CNK * CD];  // 64 MB  tf32-rounded K
__device__ float g_xr[CB * CNQ * CD];  // 32 MB  tf32-rounded LN0 out

__device__ __forceinline__ float to_tf32(float x) {
    float r;
    asm("cvt.rna.tf32.f32 %0, %1;" : "=f"(r) : "f"(x));
    return r;
}

__device__ __forceinline__ uint32_t smem_u32(const void* p) {
    uint32_t a;
    asm("{ .reg .u64 t; cvta.to.shared.u64 t, %1; cvt.u32.u64 %0, t; }"
        : "=r"(a) : "l"(p));
    return a;
}

__device__ __forceinline__ void cpasync16(uint32_t dst, const float* src) {
    asm volatile("cp.async.cg.shared.global [%0], [%1], 16;"
                 :: "r"(dst), "l"(src));
}
#define CP_COMMIT() asm volatile("cp.async.commit_group;" ::: "memory")
#define CP_WAIT(n)  asm volatile("cp.async.wait_group %0;" :: "n"(n) : "memory")

typedef wmma::fragment<wmma::matrix_a, 16, 16, 8, wmma::precision::tf32, wmma::row_major> AFrag;
typedef wmma::fragment<wmma::matrix_b, 16, 16, 8, wmma::precision::tf32, wmma::row_major> BFragRow;
typedef wmma::fragment<wmma::matrix_b, 16, 16, 8, wmma::precision::tf32, wmma::col_major> BFragCol;
typedef wmma::fragment<wmma::accumulator, 16, 16, 8, float> CFrag;

// ===========================================================================
// 3-stage cp.async pipelined tf32 GEMM.
// C[M,1024] = A[M,1024] @ W[1024,1024] + bias          (mode 0)
// C = R + relu(A @ W + bias)                           (mode 1)
// A, W pre-rounded to tf32 (RNA). 128x128 tile, BK=16, 256 threads / 8 warps.
// ===========================================================================
static constexpr int GS      = 3;
static constexpr int AS_LD   = 20;
static constexpr int BS_LD   = 132;
static constexpr int A_ST_F  = 128 * AS_LD;             // 2560 floats
static constexpr int STAGE_F = A_ST_F + 16 * BS_LD;     // 4672 floats
static constexpr int CS_LD   = 132;
static constexpr int GEMM_SMEM_BYTES = 128 * CS_LD * 4; // 67584 >= 3*4672*4

__global__ __launch_bounds__(256)
void gemm_pipe_kernel(const float* __restrict__ A, const float* __restrict__ W,
                      const float* __restrict__ bias, const float* __restrict__ R,
                      float* __restrict__ C, int relu_residual)
{
    extern __shared__ float sm[];
    const int tid = threadIdx.x;
    const int w   = tid >> 5;
    const int wm  = w & 3;        // 32-row group
    const int wn  = w >> 2;       // 64-col group
    const int r0  = blockIdx.y * 128;
    const int n0  = blockIdx.x * 128;

    const int a_row = tid >> 1;
    const int a_c0  = (tid & 1) * 8;
    const int b_row = tid >> 4;
    const int b_c0  = (tid & 15) * 8;
    const float* Ap = A + (size_t)(r0 + a_row) * 1024 + a_c0;
    const float* Bp = W + (size_t)b_row * 1024 + n0 + b_c0;

    const uint32_t sbase = smem_u32(sm);
    const uint32_t as_dst = sbase + (a_row * AS_LD + a_c0) * 4;
    const uint32_t bs_dst = sbase + (A_ST_F + b_row * BS_LD + b_c0) * 4;

    CFrag acc[2][4];
#pragma unroll
    for (int i = 0; i < 2; ++i)
#pragma unroll
        for (int j = 0; j < 4; ++j) wmma::fill_fragment(acc[i][j], 0.f);

    // prologue: stages 0,1 <- chunks 0,1
#pragma unroll
    for (int s = 0; s < GS - 1; ++s) {
        const uint32_t so = s * STAGE_F * 4;
        const float* ap = Ap + s * 16;
        const float* bp = Bp + (size_t)s * 16 * 1024;
        cpasync16(as_dst + so,      ap);
        cpasync16(as_dst + so + 16, ap + 4);
        cpasync16(bs_dst + so,      bp);
        cpasync16(bs_dst + so + 16, bp + 4);
        CP_COMMIT();
    }

    for (int kt = 0; kt < 64; ++kt) {
        CP_WAIT(1);            // chunk kt arrived (per-thread)
        __syncthreads();       // all threads' chunk-kt loads visible; compute kt-1 done
        if (kt + 2 < 64) {     // prefetch chunk kt+2 into stage (kt+2)%3 (free)
            const int s = (kt + 2) % GS;
            const uint32_t so = s * STAGE_F * 4;
            const float* ap = Ap + (kt + 2) * 16;
            const float* bp = Bp + (size_t)(kt + 2) * 16 * 1024;
            cpasync16(as_dst + so,      ap);
            cpasync16(as_dst + so + 16, ap + 4);
            cpasync16(bs_dst + so,      bp);
            cpasync16(bs_dst + so + 16, bp + 4);
        }
        CP_COMMIT();           // commit (possibly empty) to keep group count uniform

        const float* As = sm + (kt % GS) * STAGE_F;
        const float* Bs = As + A_ST_F;
#pragma unroll
        for (int ks = 0; ks < 16; ks += 8) {
            AFrag af[2];
#pragma unroll
            for (int i = 0; i < 2; ++i)
                wmma::load_matrix_sync(af[i], &As[(wm * 32 + i * 16) * AS_LD + ks], AS_LD);
            BFragRow bf[4];
#pragma unroll
            for (int j = 0; j < 4; ++j)
                wmma::load_matrix_sync(bf[j], &Bs[ks * BS_LD + wn * 64 + j * 16], BS_LD);
#pragma unroll
            for (int i = 0; i < 2; ++i)
#pragma unroll
                for (int j = 0; j < 4; ++j)
                    wmma::mma_sync(acc[i][j], af[i], bf[j], acc[i][j]);
        }
    }

    CP_WAIT(0);
    __syncthreads();

    // epilogue via smem staging (alias over stage buffers)
    float* Cs = sm;
#pragma unroll
    for (int i = 0; i < 2; ++i)
#pragma unroll
        for (int j = 0; j < 4; ++j)
            wmma::store_matrix_sync(&Cs[(wm * 32 + i * 16) * CS_LD + wn * 64 + j * 16],
                                    acc[i][j], CS_LD, wmma::mem_row_major);
    __syncthreads();

    const int er  = tid >> 1;
    const int ec0 = (tid & 1) * 64;
#pragma unroll
    for (int q = 0; q < 16; ++q) {
        const int c = ec0 + q * 4;
        float4 bb = *(const float4*)(bias + n0 + c);
        const float* cp = &Cs[er * CS_LD + c];
        float4 val;
        val.x = cp[0] + bb.x; val.y = cp[1] + bb.y;
        val.z = cp[2] + bb.z; val.w = cp[3] + bb.w;
        if (relu_residual) {
            float4 rr = *(const float4*)(R + (size_t)(r0 + er) * 1024 + n0 + c);
            val.x = rr.x + fmaxf(val.x, 0.f);
            val.y = rr.y + fmaxf(val.y, 0.f);
            val.z = rr.z + fmaxf(val.z, 0.f);
            val.w = rr.w + fmaxf(val.w, 0.f);
        }
        *(float4*)(C + (size_t)(r0 + er) * 1024 + n0 + c) = val;
    }
}

// elementwise tf32 RNA rounding (float4)
__global__ __launch_bounds__(256)
void round_tf32_kernel(const float* __restrict__ in, float* __restrict__ out)
{
    const size_t i = (size_t)blockIdx.x * blockDim.x + threadIdx.x;
    float4 v = ((const float4*)in)[i];
    v.x = to_tf32(v.x); v.y = to_tf32(v.y);
    v.z = to_tf32(v.z); v.w = to_tf32(v.w);
    ((float4*)out)[i] = v;
}

// ===========================================================================
// Attention (unchanged from R4): wmma tf32, no-max softmax.
// ===========================================================================
static constexpr int ATT_T_LD = 132;
static constexpr int ATT_P_LD = 68;
static constexpr int ATT_QS_OFF = 0;
static constexpr int ATT_KV_OFF = 64 * ATT_T_LD;
static constexpr int ATT_PS_OFF = 2 * 64 * ATT_T_LD;
static constexpr int ATT_L_OFF  = ATT_PS_OFF + 64 * ATT_P_LD;
static constexpr int ATT_SMEM_BYTES = (ATT_L_OFF + 64) * 4;

__global__ __launch_bounds__(256, 2)
void attn_tc_kernel(const float* __restrict__ q, const float* __restrict__ k,
                    const float* __restrict__ v, float* __restrict__ x)
{
    extern __shared__ float sm[];
    float* Qs = sm + ATT_QS_OFF;
    float* KV = sm + ATT_KV_OFF;
    float* Ps = sm + ATT_PS_OFF;
    float* lrow = sm + ATT_L_OFF;

    const int b  = blockIdx.z;
    const int h  = blockIdx.y;
    const int q0 = blockIdx.x * 64;

    const float* qb = q + ((size_t)(b * CNQ + q0)) * CD + h * CDH;
    const float* kb = k + (size_t)b * CNK * CD + h * CDH;
    const float* vb = v + (size_t)b * CNK * CD + h * CDH;
    float*       xb = x + ((size_t)(b * CNQ + q0)) * CD + h * CDH;

    const int tid = threadIdx.x;
    const int w   = tid >> 5;
    const int wmS = w & 3;
    const int wnS = w >> 2;
    const int wmO = w & 3;
    const int wnO = w >> 2;

    {
        const int r  = tid >> 2;
        const int c0 = (tid & 3) * 32;
#pragma unroll
        for (int u = 0; u < 8; ++u) {
            float4 vq = *(const float4*)(qb + (size_t)r * CD + c0 + u * 4);
            float* p = &Qs[r * ATT_T_LD + c0 + u * 4];
            p[0] = to_tf32(vq.x); p[1] = to_tf32(vq.y);
            p[2] = to_tf32(vq.z); p[3] = to_tf32(vq.w);
        }
        if (tid < 64) lrow[tid] = 0.f;
    }

    CFrag oacc[4];
#pragma unroll
    for (int j = 0; j < 4; ++j) wmma::fill_fragment(oacc[j], 0.f);

    const float scale = 0.03125f;

    for (int kt = 0; kt < CNK / 64; ++kt) {
        const int j0 = kt * 64;
        __syncthreads();
        {
            const int r  = tid >> 2;
            const int c0 = (tid & 3) * 32;
#pragma unroll
            for (int u = 0; u < 8; ++u) {
                float4 kv4 = *(const float4*)(kb + (size_t)(j0 + r) * CD + c0 + u * 4);
                float* p = &KV[r * ATT_T_LD + c0 + u * 4];
                p[0] = to_tf32(kv4.x); p[1] = to_tf32(kv4.y);
                p[2] = to_tf32(kv4.z); p[3] = to_tf32(kv4.w);
            }
        }
        __syncthreads();
        {
            CFrag sacc[2];
            wmma::fill_fragment(sacc[0], 0.f);
            wmma::fill_fragment(sacc[1], 0.f);
#pragma unroll
            for (int kk = 0; kk < 128; kk += 8) {
                AFrag af;
                wmma::load_matrix_sync(af, &Qs[(wmS * 16) * ATT_T_LD + kk], ATT_T_LD);
                BFragCol bf[2];
#pragma unroll
                for (int j = 0; j < 2; ++j)
                    wmma::load_matrix_sync(bf[j], &KV[(wnS * 32 + j * 16) * ATT_T_LD + kk], ATT_T_LD);
#pragma unroll
                for (int j = 0; j < 2; ++j)
                    wmma::mma_sync(sacc[j], af, bf[j], sacc[j]);
            }
#pragma unroll
            for (int j = 0; j < 2; ++j)
                wmma::store_matrix_sync(&Ps[(wmS * 16) * ATT_P_LD + wnS * 32 + j * 16],
                                        sacc[j], ATT_P_LD, wmma::mem_row_major);
        }
        __syncthreads();
        {
            const int r  = tid >> 2;
            const int c0 = (tid & 3) * 32;
#pragma unroll
            for (int u = 0; u < 8; ++u) {
                float4 vv = *(const float4*)(vb + (size_t)(j0 + r) * CD + c0 + u * 4);
                float* p = &KV[r * ATT_T_LD + c0 + u * 4];
                p[0] = to_tf32(vv.x); p[1] = to_tf32(vv.y);
                p[2] = to_tf32(vv.z); p[3] = to_tf32(vv.w);
            }
            const int pc0 = (tid & 3) * 16;
            float* pr = &Ps[r * ATT_P_LD + pc0];
            float sum = 0.f;
#pragma unroll
            for (int u = 0; u < 16; ++u) {
                float e = __expf(pr[u] * scale);
                sum += e;
                pr[u] = to_tf32(e);
            }
            sum += __shfl_xor_sync(0xffffffffu, sum, 1);
            sum += __shfl_xor_sync(0xffffffffu, sum, 2);
            if ((tid & 3) == 0) lrow[r] += sum;
        }
        __syncthreads();
#pragma unroll
        for (int jj = 0; jj < 64; jj += 8) {
            AFrag af;
            wmma::load_matrix_sync(af, &Ps[(wmO * 16) * ATT_P_LD + jj], ATT_P_LD);
            BFragRow bf[4];
#pragma unroll
            for (int j = 0; j < 4; ++j)
                wmma::load_matrix_sync(bf[j], &KV[jj * ATT_T_LD + wnO * 64 + j * 16], ATT_T_LD);
#pragma unroll
            for (int j = 0; j < 4; ++j)
                wmma::mma_sync(oacc[j], af, bf[j], oacc[j]);
        }
    }

    __syncthreads();
#pragma unroll
    for (int j = 0; j < 4; ++j)
        wmma::store_matrix_sync(&KV[(wmO * 16) * ATT_T_LD + wnO * 64 + j * 16],
                                oacc[j], ATT_T_LD, wmma::mem_row_major);
    __syncthreads();
    {
        const int r  = tid >> 2;
        const int c0 = (tid & 3) * 32;
        const float inv = 1.f / lrow[r];
#pragma unroll
        for (int u = 0; u < 8; ++u) {
            const int c = c0 + u * 4;
            float4 qres = *(const float4*)(qb + (size_t)r * CD + c);
            const float* op = &KV[r * ATT_T_LD + c];
            float4 ov;
            ov.x = fmaf(op[0], inv, qres.x);
            ov.y = fmaf(op[1], inv, qres.y);
            ov.z = fmaf(op[2], inv, qres.z);
            ov.w = fmaf(op[3], inv, qres.w);
            *(float4*)(xb + (size_t)r * CD + c) = ov;
        }
    }
}

// ===========================================================================
// Row LayerNorm over 1024 columns.
// ===========================================================================
__global__ __launch_bounds__(256)
void ln_kernel(const float* __restrict__ in, float* __restrict__ out,
               const float* __restrict__ g, const float* __restrict__ bta)
{
    __shared__ float red_s[8], red_s2[8];
    __shared__ float mu_s, rs_s;
    const int row = blockIdx.x;
    const int tid = threadIdx.x;
    const float* rp = in + (size_t)row * 1024;

    float4 xv = *(const float4*)(rp + tid * 4);
    float s  = xv.x + xv.y + xv.z + xv.w;
    float s2 = xv.x * xv.x + xv.y * xv.y + xv.z * xv.z + xv.w * xv.w;
#pragma unroll
    for (int off = 16; off >= 1; off >>= 1) {
        s  += __shfl_xor_sync(0xffffffffu, s,  off);
        s2 += __shfl_xor_sync(0xffffffffu, s2, off);
    }
    if ((tid & 31) == 0) { red_s[tid >> 5] = s; red_s2[tid >> 5] = s2; }
    __syncthreads();
    if (tid == 0) {
        float a = 0.f, a2 = 0.f;
#pragma unroll
        for (int wq = 0; wq < 8; ++wq) { a += red_s[wq]; a2 += red_s2[wq]; }
        const float mu  = a * (1.f / 1024.f);
        const float var = a2 * (1.f / 1024.f) - mu * mu;
        mu_s = mu;
        rs_s = rsqrtf(var + 1e-5f);
    }
    __syncthreads();
    const float mu = mu_s, rs = rs_s;
    float4 gv = *(const float4*)(g + tid * 4);
    float4 bv = *(const float4*)(bta + tid * 4);
    float4 ov;
    ov.x = (xv.x - mu) * rs * gv.x + bv.x;
    ov.y = (xv.y - mu) * rs * gv.y + bv.y;
    ov.z = (xv.z - mu) * rs * gv.z + bv.z;
    ov.w = (xv.w - mu) * rs * gv.w + bv.w;
    *(float4*)(out + (size_t)row * 1024 + tid * 4) = ov;
}

// ===========================================================================
extern "C" void kernel_launch(void* const* d_in, const int* in_sizes, int n_in,
                              void* d_out, int out_size)
{
    const float* Q  = (const float*)d_in[0];
    const float* K  = (const float*)d_in[1];
    const float* Wq = (const float*)d_in[2];
    const float* bq = (const float*)d_in[3];
    const float* Wk = (const float*)d_in[4];
    const float* bk = (const float*)d_in[5];
    const float* Wv = (const float*)d_in[6];
    const float* bv = (const float*)d_in[7];
    const float* Wo = (const float*)d_in[8];
    const float* bo = (const float*)d_in[9];
    const float* g0 = (const float*)d_in[10];
    const float* b0 = (const float*)d_in[11];
    const float* g1 = (const float*)d_in[12];
    const float* b1 = (const float*)d_in[13];
    float* out = (float*)d_out;

    float *qp, *kp, *vp, *xp, *yp, *wrp, *qrp, *krp, *xrp;
    cudaGetSymbolAddress((void**)&qp,  g_q);
    cudaGetSymbolAddress((void**)&kp,  g_k);
    cudaGetSymbolAddress((void**)&vp,  g_v);
    cudaGetSymbolAddress((void**)&xp,  g_x);
    cudaGetSymbolAddress((void**)&yp,  g_y);
    cudaGetSymbolAddress((void**)&wrp, g_wr);
    cudaGetSymbolAddress((void**)&qrp, g_qr);
    cudaGetSymbolAddress((void**)&krp, g_kr);
    cudaGetSymbolAddress((void**)&xrp, g_xr);

    cudaFuncSetAttribute(gemm_pipe_kernel,
                         cudaFuncAttributeMaxDynamicSharedMemorySize,
                         GEMM_SMEM_BYTES);
    cudaFuncSetAttribute(attn_tc_kernel,
                         cudaFuncAttributeMaxDynamicSharedMemorySize,
                         ATT_SMEM_BYTES);

    // prep: tf32-round activations + weights (row-major, no transpose)
    round_tf32_kernel<<<CB * CNQ * CD / 1024, 256>>>(Q, qrp);
    round_tf32_kernel<<<CB * CNK * CD / 1024, 256>>>(K, krp);
    round_tf32_kernel<<<CD * CD / 1024, 256>>>(Wq, wrp + 0 * CD * CD);
    round_tf32_kernel<<<CD * CD / 1024, 256>>>(Wk, wrp + 1 * CD * CD);
    round_tf32_kernel<<<CD * CD / 1024, 256>>>(Wv, wrp + 2 * CD * CD);
    round_tf32_kernel<<<CD * CD / 1024, 256>>>(Wo, wrp + 3 * CD * CD);

    // projections (pipelined tf32 wmma)
    gemm_pipe_kernel<<<dim3(8,  64), 256, GEMM_SMEM_BYTES>>>(qrp, wrp + 0 * CD * CD, bq, nullptr, qp, 0);
    gemm_pipe_kernel<<<dim3(8, 128), 256, GEMM_SMEM_BYTES>>>(krp, wrp + 1 * CD * CD, bk, nullptr, kp, 0);
    gemm_pipe_kernel<<<dim3(8, 128), 256, GEMM_SMEM_BYTES>>>(krp, wrp + 2 * CD * CD, bv, nullptr, vp, 0);

    // attention + residual
    attn_tc_kernel<<<dim3(CNQ / 64, CH, CB), 256, ATT_SMEM_BYTES>>>(qp, kp, vp, xp);
    // LN0 (in place)
    ln_kernel<<<CB * CNQ, 256>>>(xp, xp, g0, b0);
    // y = x + relu(x @ Wo + bo)
    round_tf32_kernel<<<CB * CNQ * CD / 1024, 256>>>(xp, xrp);
    gemm_pipe_kernel<<<dim3(8, 64), 256, GEMM_SMEM_BYTES>>>(xrp, wrp + 3 * CD * CD, bo, xp, yp, 1);
    // LN1 -> out
    ln_kernel<<<CB * CNQ, 256>>>(yp, out, g1, b1);
}